// round 15
// baseline (speedup 1.0000x reference)
#include <cuda_runtime.h>
#include <cuda_fp16.h>
#include <math.h>
#include <stdint.h>

#define NN 100000
#define EE 1600000
#define RR 8
#define GG 128
#define HH 64
#define CC 512   // RR*HH
#define SCAN_B 512
#define NBLK ((NN + SCAN_B - 1) / SCAN_B)   // 196

// ---------------- scratch ----------------
__device__ __half g_xw[(size_t)RR * NN * HH];  // [r][n][h] fp16
__device__ __half g_xa[(size_t)NN * GG];       // fp16 input features
__device__ __half g_WT[GG * CC];               // [r*64+o][k] fp16 (n-major)
__device__ float g_sq[RR * NN];
__device__ float g_sk[RR * NN];
__device__ int   g_rs[EE];
__device__ int   g_dstl[EE];
__device__ int   g_rank[EE];
__device__ int   g_sorted[EE];
__device__ int   g_cnt[NN];
__device__ int   g_off[NN];
__device__ int   g_scan[NN];
__device__ int   g_bsum[256];
__device__ int   g_bpre[256];
__device__ __half g_x1[NN * HH];               // fp16 layer-1 output
__device__ float g_bnsum[HH];
__device__ float g_bnsqs[HH];
__device__ float g_bnscale[HH];
__device__ float g_bnshift[HH];

// ---------------- sort-by-dst pipeline ----------------
__global__ void k_zero() {
    int i = blockIdx.x * blockDim.x + threadIdx.x;
    if (i < NN) g_cnt[i] = 0;
    if (i < HH) { g_bnsum[i] = 0.f; g_bnsqs[i] = 0.f; }
}

__global__ void k_decode(const int* __restrict__ ei, const int* __restrict__ et) {
    int e = blockIdx.x * blockDim.x + threadIdx.x;
    if (e >= EE) return;
    int s = min(max(ei[e], 0), NN - 1);
    int d = min(max(ei[EE + e], 0), NN - 1);
    int r = min(max(et[e], 0), RR - 1);
    g_rs[e]   = r * NN + s;
    g_dstl[e] = d;
    g_rank[e] = atomicAdd(&g_cnt[d], 1);
}

__global__ void k_scan1() {
    __shared__ int s[SCAN_B];
    int tid = threadIdx.x;
    int i = blockIdx.x * SCAN_B + tid;
    int v = (i < NN) ? g_cnt[i] : 0;
    s[tid] = v;
    __syncthreads();
    for (int d = 1; d < SCAN_B; d <<= 1) {
        int t = (tid >= d) ? s[tid - d] : 0;
        __syncthreads();
        s[tid] += t;
        __syncthreads();
    }
    if (i < NN) g_scan[i] = s[tid];
    if (tid == SCAN_B - 1) g_bsum[blockIdx.x] = s[tid];
}

__global__ void k_scan2() {
    __shared__ int s[256];
    int tid = threadIdx.x;
    int v = (tid < NBLK) ? g_bsum[tid] : 0;
    s[tid] = v;
    __syncthreads();
    for (int d = 1; d < 256; d <<= 1) {
        int t = (tid >= d) ? s[tid - d] : 0;
        __syncthreads();
        s[tid] += t;
        __syncthreads();
    }
    if (tid < NBLK) g_bpre[tid] = s[tid] - v;
}

__global__ void k_scan3() {
    int i = blockIdx.x * blockDim.x + threadIdx.x;
    if (i >= NN) return;
    g_off[i] = g_scan[i] - g_cnt[i] + g_bpre[i >> 9];
}

__global__ void k_scatter() {
    int e = blockIdx.x * blockDim.x + threadIdx.x;
    if (e >= EE) return;
    g_sorted[g_off[g_dstl[e]] + g_rank[e]] = g_rs[e];
}

// W [R,K,H] -> WT [r*64+o][k] fp16
__global__ void k_wt(const float* __restrict__ W, int K) {
    int idx = blockIdx.x * blockDim.x + threadIdx.x;
    if (idx >= K * CC) return;
    int c = idx / K, i = idx % K;
    int r = c >> 6, o = c & 63;
    g_WT[idx] = __float2half_rn(W[((size_t)r * K + i) * HH + o]);
}

// x -> g_xa fp16
__global__ void k_cvtA(const float* __restrict__ x) {
    int i = blockIdx.x * blockDim.x + threadIdx.x;
    if (i >= NN * (GG / 4)) return;
    float4 v = ((const float4*)x)[i];
    __half2 h0 = __floats2half2_rn(v.x, v.y);
    __half2 h1 = __floats2half2_rn(v.z, v.w);
    ((uint2*)g_xa)[i] = make_uint2(*(uint32_t*)&h0, *(uint32_t*)&h1);
}

// ---------------- fp16 tensor-core GEMM + fused scores ----------------
// Block: 128 rows x 64 cols (ONE relation), 8 warps of 16x64 -> 32 acc regs.
// 3 CTAs/SM via __launch_bounds__(256,3).
#define PADH 40

__device__ __forceinline__ void cpa16(uint32_t smem_addr, const void* gptr, int sz) {
    asm volatile("cp.async.ca.shared.global [%0], [%1], 16, %2;\n"
                 :: "r"(smem_addr), "l"(gptr), "r"(sz));
}

__global__ void __launch_bounds__(256, 3)
k_gemm(int M, int K, int useX1,
       const float* __restrict__ qv_g, const float* __restrict__ kv_g) {
    const __half* __restrict__ A = useX1 ? g_x1 : g_xa;
    __shared__ __half Ah[2][128 * PADH];
    __shared__ __half Bh[2][64 * PADH];
    __shared__ float qs[64], ks[64];

    int rel = blockIdx.x;                 // one relation per block
    int rowBase = blockIdx.y * 128;
    int tid = threadIdx.x;
    int warp = tid >> 5, lane = tid & 31;
    int wr = warp;                        // rows wr*16 .. wr*16+15
    int g = lane >> 2, t = lane & 3;

    uint32_t AhS0 = (uint32_t)__cvta_generic_to_shared(Ah[0]);
    uint32_t AhS1 = (uint32_t)__cvta_generic_to_shared(Ah[1]);
    uint32_t BhS0 = (uint32_t)__cvta_generic_to_shared(Bh[0]);
    uint32_t BhS1 = (uint32_t)__cvta_generic_to_shared(Bh[1]);

    if (tid < 64)        qs[tid] = qv_g[tid];
    else if (tid < 128)  ks[tid - 64] = kv_g[tid - 64];

    float acc[8][4];
    #pragma unroll
    for (int j = 0; j < 8; j++)
        #pragma unroll
        for (int l = 0; l < 4; l++) acc[j][l] = 0.f;

    int nChunks = K >> 5;
    // A loader: 128 rows x 4 vec16 -> 512 vecs, 2 per thread
    int av0 = tid * 2, av1 = tid * 2 + 1;
    int arow0 = av0 >> 2, ac80 = (av0 & 3) * 8;
    int arow1 = av1 >> 2, ac81 = (av1 & 3) * 8;
    // B loader: 64 rows x 4 vec16 -> 256 vecs, 1 per thread
    int brow = tid >> 2, bc8 = (tid & 3) * 8;

    int lm_row = (lane & 7) + ((lane >> 3) & 1) * 8;
    int lm_c8  = (lane >> 4) * 8;
    int bl_row = lane & 7;
    int bl_k8  = ((lane >> 3) & 1) * 8;

    int ag0 = rowBase + arow0, ag1 = rowBase + arow1;
    bool ok0 = (ag0 < M), ok1 = (ag1 < M);
    const __half* aSrc0 = A + (size_t)ag0 * K;
    const __half* aSrc1 = A + (size_t)ag1 * K;
    const __half* bSrc = g_WT + (size_t)(rel * 64 + brow) * K;

    // prefetch chunk 0 into buf 0
    cpa16(AhS0 + (arow0 * PADH + ac80) * 2, aSrc0 + ac80, ok0 ? 16 : 0);
    cpa16(AhS0 + (arow1 * PADH + ac81) * 2, aSrc1 + ac81, ok1 ? 16 : 0);
    cpa16(BhS0 + (brow * PADH + bc8) * 2, bSrc + bc8, 16);
    asm volatile("cp.async.commit_group;\n");

    for (int c = 0; c < nChunks; c++) {
        int cur = c & 1;
        if (c + 1 < nChunks) {
            int kb = (c + 1) << 5;
            uint32_t AhN = cur ? AhS0 : AhS1;
            uint32_t BhN = cur ? BhS0 : BhS1;
            cpa16(AhN + (arow0 * PADH + ac80) * 2, aSrc0 + kb + ac80, ok0 ? 16 : 0);
            cpa16(AhN + (arow1 * PADH + ac81) * 2, aSrc1 + kb + ac81, ok1 ? 16 : 0);
            cpa16(BhN + (brow * PADH + bc8) * 2, bSrc + kb + bc8, 16);
            asm volatile("cp.async.commit_group;\n");
            asm volatile("cp.async.wait_group 1;\n");
        } else {
            asm volatile("cp.async.wait_group 0;\n");
        }
        __syncthreads();

        uint32_t AhC = cur ? AhS1 : AhS0;
        uint32_t BhC = cur ? BhS1 : BhS0;

        #pragma unroll
        for (int ks16 = 0; ks16 < 2; ks16++) {
            uint32_t af[4];
            {
                int row = wr * 16 + lm_row;
                uint32_t addr = AhC + (row * PADH + ks16 * 16 + lm_c8) * 2;
                asm volatile(
                    "ldmatrix.sync.aligned.m8n8.x4.shared.b16 {%0,%1,%2,%3}, [%4];\n"
                    : "=r"(af[0]), "=r"(af[1]), "=r"(af[2]), "=r"(af[3])
                    : "r"(addr));
            }
            #pragma unroll
            for (int nt = 0; nt < 8; nt++) {
                uint32_t bf0, bf1;
                uint32_t baddr = BhC +
                    ((nt * 8 + bl_row) * PADH + ks16 * 16 + bl_k8) * 2;
                asm volatile(
                    "ldmatrix.sync.aligned.m8n8.x2.shared.b16 {%0,%1}, [%2];\n"
                    : "=r"(bf0), "=r"(bf1) : "r"(baddr));
                asm volatile(
                    "mma.sync.aligned.m16n8k16.row.col.f32.f16.f16.f32 "
                    "{%0,%1,%2,%3}, {%4,%5,%6,%7}, {%8,%9}, {%0,%1,%2,%3};\n"
                    : "+f"(acc[nt][0]), "+f"(acc[nt][1]),
                      "+f"(acc[nt][2]), "+f"(acc[nt][3])
                    : "r"(af[0]), "r"(af[1]), "r"(af[2]), "r"(af[3]),
                      "r"(bf0), "r"(bf1));
            }
        }
        __syncthreads();
    }

    float qv[16], kv[16];
    #pragma unroll
    for (int nt = 0; nt < 8; nt++) {
        int o0 = nt * 8 + 2 * t;
        qv[2 * nt] = qs[o0]; qv[2 * nt + 1] = qs[o0 + 1];
        kv[2 * nt] = ks[o0]; kv[2 * nt + 1] = ks[o0 + 1];
    }
    __half2* xwh = (__half2*)g_xw;
    #pragma unroll
    for (int h = 0; h < 2; h++) {
        int row_l = wr * 16 + g + h * 8;
        int grow = rowBase + row_l;
        bool ok = (grow < M);
        float pq = 0.f, pk = 0.f;
        #pragma unroll
        for (int nt = 0; nt < 8; nt++) {
            float c0 = acc[nt][h * 2 + 0];
            float c1 = acc[nt][h * 2 + 1];
            if (ok) {
                xwh[((size_t)rel * NN + grow) * 32 + nt * 4 + t] =
                    __floats2half2_rn(c0, c1);
            }
            pq += c0 * qv[2 * nt] + c1 * qv[2 * nt + 1];
            pk += c0 * kv[2 * nt] + c1 * kv[2 * nt + 1];
        }
        pq += __shfl_xor_sync(0xffffffffu, pq, 1);
        pq += __shfl_xor_sync(0xffffffffu, pq, 2);
        pk += __shfl_xor_sync(0xffffffffu, pk, 1);
        pk += __shfl_xor_sync(0xffffffffu, pk, 2);
        if (ok && t == 0) {
            g_sq[rel * NN + grow] = pq;
            g_sk[rel * NN + grow] = pk;
        }
    }
}

// ---------------- segmented softmax-aggregate: one warp per node ----------------
__global__ void k_agg(const float* __restrict__ b, float* outParam, int mode) {
    int gw = (blockIdx.x * blockDim.x + threadIdx.x) >> 5;
    int lane = threadIdx.x & 31;
    if (gw >= NN) return;
    int node = gw;
    int beg = g_off[node];
    int cnt = g_cnt[node];
    const __half2* xwh = (const __half2*)g_xw;

    float2 acc = make_float2(0.f, 0.f);
    float denom = 0.f;

    if (cnt <= 32) {
        int rs_l = 0;
        float a_l = -INFINITY;
        if (lane < cnt) {
            rs_l = g_sorted[beg + lane];
            int r = rs_l / NN;
            float a = g_sq[r * NN + node] + g_sk[rs_l];
            a_l = a > 0.f ? a : 0.2f * a;
        }
        float m = a_l;
        #pragma unroll
        for (int off = 16; off; off >>= 1)
            m = fmaxf(m, __shfl_xor_sync(0xffffffffu, m, off));
        float w_l = (lane < cnt) ? __expf(a_l - m) : 0.f;
        float ds = w_l;
        #pragma unroll
        for (int off = 16; off; off >>= 1)
            ds += __shfl_xor_sync(0xffffffffu, ds, off);
        denom = ds;
        int i = 0;
        for (; i + 2 <= cnt; i += 2) {
            int rs0 = __shfl_sync(0xffffffffu, rs_l, i);
            int rs1 = __shfl_sync(0xffffffffu, rs_l, i + 1);
            float w0 = __shfl_sync(0xffffffffu, w_l, i);
            float w1 = __shfl_sync(0xffffffffu, w_l, i + 1);
            float2 v0 = __half22float2(xwh[(size_t)rs0 * 32 + lane]);
            float2 v1 = __half22float2(xwh[(size_t)rs1 * 32 + lane]);
            acc.x += w0 * v0.x + w1 * v1.x;
            acc.y += w0 * v0.y + w1 * v1.y;
        }
        if (i < cnt) {
            int rs0 = __shfl_sync(0xffffffffu, rs_l, i);
            float w0 = __shfl_sync(0xffffffffu, w_l, i);
            float2 v0 = __half22float2(xwh[(size_t)rs0 * 32 + lane]);
            acc.x += w0 * v0.x;
            acc.y += w0 * v0.y;
        }
    } else {
        float m = -INFINITY;
        for (int i = lane; i < cnt; i += 32) {
            int rs = g_sorted[beg + i];
            int r = rs / NN;
            float a = g_sq[r * NN + node] + g_sk[rs];
            a = a > 0.f ? a : 0.2f * a;
            m = fmaxf(m, a);
        }
        #pragma unroll
        for (int off = 16; off; off >>= 1)
            m = fmaxf(m, __shfl_xor_sync(0xffffffffu, m, off));
        for (int i = 0; i < cnt; i++) {
            int rs = g_sorted[beg + i];
            int r = rs / NN;
            float a = g_sq[r * NN + node] + g_sk[rs];
            a = a > 0.f ? a : 0.2f * a;
            float w = __expf(a - m);
            denom += w;
            float2 v = __half22float2(xwh[(size_t)rs * 32 + lane]);
            acc.x += w * v.x;
            acc.y += w * v.y;
        }
    }

    float inv = 1.f / (denom + 1e-16f);
    float2 bb = ((const float2*)b)[lane];
    float ox = acc.x * inv + bb.x;
    float oy = acc.y * inv + bb.y;
    if (mode == 1) {
        ox = fmaxf(ox, 0.f);
        oy = fmaxf(oy, 0.f);
        ((__half2*)g_x1)[(size_t)node * 32 + lane] = __floats2half2_rn(ox, oy);
    } else {
        ((float2*)outParam)[(size_t)node * 32 + lane] = make_float2(ox, oy);
    }
}

// ---------------- batchnorm ----------------
__global__ void k_bnstats(const float* __restrict__ out) {
    int gw = (blockIdx.x * blockDim.x + threadIdx.x) >> 5;
    int lane = threadIdx.x & 31;
    const int CHUNK = 98;
    int n0 = gw * CHUNK;
    float2 s = make_float2(0.f, 0.f), s2 = make_float2(0.f, 0.f);
    for (int n = n0; n < n0 + CHUNK && n < NN; n++) {
        float2 v = ((const float2*)out)[(size_t)n * 32 + lane];
        s.x += v.x; s.y += v.y;
        s2.x += v.x * v.x; s2.y += v.y * v.y;
    }
    atomicAdd(&g_bnsum[2 * lane], s.x);     atomicAdd(&g_bnsum[2 * lane + 1], s.y);
    atomicAdd(&g_bnsqs[2 * lane], s2.x);    atomicAdd(&g_bnsqs[2 * lane + 1], s2.y);
}

__global__ void k_bnfinal(const float* __restrict__ gamma, const float* __restrict__ beta) {
    int h = threadIdx.x;
    if (h < HH) {
        float mean = g_bnsum[h] * (1.f / NN);
        float var  = g_bnsqs[h] * (1.f / NN) - mean * mean;
        float sc = gamma[h] * rsqrtf(var + 1e-5f);
        g_bnscale[h] = sc;
        g_bnshift[h] = beta[h] - mean * sc;
    }
}

__global__ void k_bnapply(float* __restrict__ out) {
    int t = blockIdx.x * blockDim.x + threadIdx.x;
    if (t >= NN * 16) return;
    int h4 = t & 15;
    float4 v  = ((float4*)out)[t];
    float4 sc = ((const float4*)g_bnscale)[h4];
    float4 sh = ((const float4*)g_bnshift)[h4];
    v.x = v.x * sc.x + sh.x; v.x = v.x > 0.f ? v.x : 0.01f * v.x;
    v.y = v.y * sc.y + sh.y; v.y = v.y > 0.f ? v.y : 0.01f * v.y;
    v.z = v.z * sc.z + sh.z; v.z = v.z > 0.f ? v.z : 0.01f * v.z;
    v.w = v.w * sc.w + sh.w; v.w = v.w > 0.f ? v.w : 0.01f * v.w;
    ((float4*)out)[t] = v;
}

// ---------------- launch ----------------
extern "C" void kernel_launch(void* const* d_in, const int* in_sizes, int n_in,
                              void* d_out, int out_size) {
    const float* x     = (const float*)d_in[0];
    const int*   ei    = (const int*)d_in[1];
    const int*   et    = (const int*)d_in[2];
    const float* W1    = (const float*)d_in[3];
    const float* q1    = (const float*)d_in[4];
    const float* k1    = (const float*)d_in[5];
    const float* b1    = (const float*)d_in[6];
    const float* W2    = (const float*)d_in[7];
    const float* q2    = (const float*)d_in[8];
    const float* k2    = (const float*)d_in[9];
    const float* b2    = (const float*)d_in[10];
    const float* gamma = (const float*)d_in[11];
    const float* beta  = (const float*)d_in[12];
    float* out = (float*)d_out;

    const int TPB = 256;
    dim3 gemmGrid(RR, (NN + 127) / 128);

    k_zero<<<(NN + TPB - 1) / TPB, TPB>>>();                       // 0
    k_cvtA<<<(NN * 32 + TPB - 1) / TPB, TPB>>>(x);                 // 1
    k_wt<<<(GG * CC + TPB - 1) / TPB, TPB>>>(W1, GG);              // 2
    k_gemm<<<gemmGrid, TPB>>>(NN, GG, 0, q1, k1);                  // 3 <- profiled
    k_decode<<<(EE + TPB - 1) / TPB, TPB>>>(ei, et);               // 4
    k_scan1<<<NBLK, SCAN_B>>>();                                   // 5
    k_scan2<<<1, 256>>>();                                         // 6
    k_scan3<<<(NN + TPB - 1) / TPB, TPB>>>();                      // 7
    k_scatter<<<(EE + TPB - 1) / TPB, TPB>>>();                    // 8
    k_agg<<<(NN * 32 + TPB - 1) / TPB, TPB>>>(b1, nullptr, 1);     // 9

    // ---- layer 2 ----
    k_wt<<<(HH * CC + TPB - 1) / TPB, TPB>>>(W2, HH);
    k_gemm<<<gemmGrid, TPB>>>(NN, HH, 1, q2, k2);
    k_agg<<<(NN * 32 + TPB - 1) / TPB, TPB>>>(b2, out, 0);

    // ---- batchnorm + leaky ----
    k_bnstats<<<(1024 * 32) / TPB, TPB>>>(out);
    k_bnfinal<<<1, HH>>>(gamma, beta);
    k_bnapply<<<(NN * 16 + TPB - 1) / TPB, TPB>>>(out);
}

// round 16
// speedup vs baseline: 1.0616x; 1.0616x over previous
#include <cuda_runtime.h>
#include <cuda_fp16.h>
#include <math.h>
#include <stdint.h>

#define NN 100000
#define EE 1600000
#define RR 8
#define GG 128
#define HH 64
#define CC 512   // RR*HH
#define SCAN_B 512
#define NBLK ((NN + SCAN_B - 1) / SCAN_B)   // 196

// ---------------- scratch ----------------
__device__ __half g_xw[(size_t)RR * NN * HH];  // [r][n][h] fp16
__device__ __half g_xa[(size_t)NN * GG];       // fp16 input features
__device__ __half g_WT[GG * CC];               // layer1 W: [r*64+o][k]
__device__ __half g_WT2[HH * CC];              // layer2 W: [r*64+o][k]
__device__ float g_sq[RR * NN];
__device__ float g_sk[RR * NN];
__device__ int   g_rs[EE];
__device__ int   g_dstl[EE];
__device__ int   g_rank[EE];
__device__ int   g_sorted[EE];
__device__ int   g_cnt[NN];
__device__ int   g_off[NN];
__device__ int   g_scan[NN];
__device__ int   g_bsum[256];
__device__ int   g_bpre[256];
__device__ __half g_x1[NN * HH];               // fp16 layer-1 output
__device__ float g_bnsum[HH];
__device__ float g_bnsqs[HH];
__device__ float g_bnscale[HH];
__device__ float g_bnshift[HH];

// ---------------- fused prep: cvtA + wt1 + wt2 + zeroing ----------------
__global__ void k_prep(const float* __restrict__ x,
                       const float* __restrict__ W1,
                       const float* __restrict__ W2) {
    int i = blockIdx.x * blockDim.x + threadIdx.x;   // 3.2M threads
    if (i < NN * (GG / 4)) {
        float4 v = ((const float4*)x)[i];
        __half2 h0 = __floats2half2_rn(v.x, v.y);
        __half2 h1 = __floats2half2_rn(v.z, v.w);
        ((uint2*)g_xa)[i] = make_uint2(*(uint32_t*)&h0, *(uint32_t*)&h1);
    }
    if (i < GG * CC) {   // wt1: [c][k], K=GG
        int c = i / GG, k = i % GG;
        int r = c >> 6, o = c & 63;
        g_WT[i] = __float2half_rn(W1[((size_t)r * GG + k) * HH + o]);
    }
    if (i < HH * CC) {   // wt2: [c][k], K=HH
        int c = i / HH, k = i % HH;
        int r = c >> 6, o = c & 63;
        g_WT2[i] = __float2half_rn(W2[((size_t)r * HH + k) * HH + o]);
    }
    if (i < NN) g_cnt[i] = 0;
    if (i < HH) { g_bnsum[i] = 0.f; g_bnsqs[i] = 0.f; }
}

// ---------------- sort-by-dst pipeline ----------------
__global__ void k_decode(const int* __restrict__ ei, const int* __restrict__ et) {
    int e = blockIdx.x * blockDim.x + threadIdx.x;
    if (e >= EE) return;
    int s = min(max(ei[e], 0), NN - 1);
    int d = min(max(ei[EE + e], 0), NN - 1);
    int r = min(max(et[e], 0), RR - 1);
    g_rs[e]   = r * NN + s;
    g_dstl[e] = d;
    g_rank[e] = atomicAdd(&g_cnt[d], 1);
}

__global__ void k_scan1() {
    __shared__ int s[SCAN_B];
    int tid = threadIdx.x;
    int i = blockIdx.x * SCAN_B + tid;
    int v = (i < NN) ? g_cnt[i] : 0;
    s[tid] = v;
    __syncthreads();
    for (int d = 1; d < SCAN_B; d <<= 1) {
        int t = (tid >= d) ? s[tid - d] : 0;
        __syncthreads();
        s[tid] += t;
        __syncthreads();
    }
    if (i < NN) g_scan[i] = s[tid];
    if (tid == SCAN_B - 1) g_bsum[blockIdx.x] = s[tid];
}

__global__ void k_scan2() {
    __shared__ int s[256];
    int tid = threadIdx.x;
    int v = (tid < NBLK) ? g_bsum[tid] : 0;
    s[tid] = v;
    __syncthreads();
    for (int d = 1; d < 256; d <<= 1) {
        int t = (tid >= d) ? s[tid - d] : 0;
        __syncthreads();
        s[tid] += t;
        __syncthreads();
    }
    if (tid < NBLK) g_bpre[tid] = s[tid] - v;
}

__global__ void k_scan3() {
    int i = blockIdx.x * blockDim.x + threadIdx.x;
    if (i >= NN) return;
    g_off[i] = g_scan[i] - g_cnt[i] + g_bpre[i >> 9];
}

__global__ void k_scatter() {
    int e = blockIdx.x * blockDim.x + threadIdx.x;
    if (e >= EE) return;
    g_sorted[g_off[g_dstl[e]] + g_rank[e]] = g_rs[e];
}

// ---------------- fp16 tensor-core GEMM + fused scores (R14 config) ----------------
#define PADH 40

__device__ __forceinline__ void cpa16(uint32_t smem_addr, const void* gptr, int sz) {
    asm volatile("cp.async.ca.shared.global [%0], [%1], 16, %2;\n"
                 :: "r"(smem_addr), "l"(gptr), "r"(sz));
}

__global__ void __launch_bounds__(256)
k_gemm(int M, int K, int useX1,
       const float* __restrict__ qv_g, const float* __restrict__ kv_g) {
    const __half* __restrict__ A = useX1 ? g_x1 : g_xa;
    const __half* __restrict__ WT = useX1 ? g_WT2 : g_WT;
    __shared__ __half Ah[2][128 * PADH];
    __shared__ __half Bh[2][128 * PADH];
    __shared__ float qs[64], ks[64];

    int rp = blockIdx.x;
    int rowBase = blockIdx.y * 128;
    int tid = threadIdx.x;
    int warp = tid >> 5, lane = tid & 31;
    int wr = warp >> 1, wc = warp & 1;
    int g = lane >> 2, t = lane & 3;

    uint32_t AhS0 = (uint32_t)__cvta_generic_to_shared(Ah[0]);
    uint32_t AhS1 = (uint32_t)__cvta_generic_to_shared(Ah[1]);
    uint32_t BhS0 = (uint32_t)__cvta_generic_to_shared(Bh[0]);
    uint32_t BhS1 = (uint32_t)__cvta_generic_to_shared(Bh[1]);

    if (tid < 64)        qs[tid] = qv_g[tid];
    else if (tid < 128)  ks[tid - 64] = kv_g[tid - 64];

    float acc[2][8][4];
    #pragma unroll
    for (int i = 0; i < 2; i++)
        #pragma unroll
        for (int j = 0; j < 8; j++)
            #pragma unroll
            for (int l = 0; l < 4; l++) acc[i][j][l] = 0.f;

    int nChunks = K >> 5;
    int lrow = tid >> 1;
    int lc8  = (tid & 1) * 8;
    int lm_row = (lane & 7) + ((lane >> 3) & 1) * 8;
    int lm_c8  = (lane >> 4) * 8;
    int bl_row = lane & 7;
    int bl_k8  = ((lane >> 3) & 1) * 8;
    int grow_l = rowBase + lrow;
    bool okA = (grow_l < M);
    const __half* aSrc = A + (size_t)grow_l * K;
    const __half* bSrc = WT + (size_t)(rp * 128 + lrow) * K;

    #pragma unroll
    for (int p = 0; p < 2; p++) {
        int c8 = lc8 + p * 16;
        cpa16(AhS0 + (lrow * PADH + c8) * 2, aSrc + c8, okA ? 16 : 0);
        cpa16(BhS0 + (lrow * PADH + c8) * 2, bSrc + c8, 16);
    }
    asm volatile("cp.async.commit_group;\n");

    for (int c = 0; c < nChunks; c++) {
        int cur = c & 1;
        if (c + 1 < nChunks) {
            int kb = (c + 1) << 5;
            uint32_t AhN = cur ? AhS0 : AhS1;
            uint32_t BhN = cur ? BhS0 : BhS1;
            #pragma unroll
            for (int p = 0; p < 2; p++) {
                int c8 = lc8 + p * 16;
                cpa16(AhN + (lrow * PADH + c8) * 2, aSrc + kb + c8, okA ? 16 : 0);
                cpa16(BhN + (lrow * PADH + c8) * 2, bSrc + kb + c8, 16);
            }
            asm volatile("cp.async.commit_group;\n");
            asm volatile("cp.async.wait_group 1;\n");
        } else {
            asm volatile("cp.async.wait_group 0;\n");
        }
        __syncthreads();

        uint32_t AhC = cur ? AhS1 : AhS0;
        uint32_t BhC = cur ? BhS1 : BhS0;

        #pragma unroll
        for (int ks16 = 0; ks16 < 2; ks16++) {
            uint32_t af[2][4];
            #pragma unroll
            for (int mt = 0; mt < 2; mt++) {
                int row = wr * 32 + mt * 16 + lm_row;
                uint32_t addr = AhC + (row * PADH + ks16 * 16 + lm_c8) * 2;
                asm volatile(
                    "ldmatrix.sync.aligned.m8n8.x4.shared.b16 {%0,%1,%2,%3}, [%4];\n"
                    : "=r"(af[mt][0]), "=r"(af[mt][1]), "=r"(af[mt][2]), "=r"(af[mt][3])
                    : "r"(addr));
            }
            #pragma unroll
            for (int nt = 0; nt < 8; nt++) {
                int nbase = wc * 64 + nt * 8;
                uint32_t bf0, bf1;
                uint32_t baddr = BhC +
                    ((nbase + bl_row) * PADH + ks16 * 16 + bl_k8) * 2;
                asm volatile(
                    "ldmatrix.sync.aligned.m8n8.x2.shared.b16 {%0,%1}, [%2];\n"
                    : "=r"(bf0), "=r"(bf1) : "r"(baddr));
                #pragma unroll
                for (int mt = 0; mt < 2; mt++) {
                    asm volatile(
                        "mma.sync.aligned.m16n8k16.row.col.f32.f16.f16.f32 "
                        "{%0,%1,%2,%3}, {%4,%5,%6,%7}, {%8,%9}, {%0,%1,%2,%3};\n"
                        : "+f"(acc[mt][nt][0]), "+f"(acc[mt][nt][1]),
                          "+f"(acc[mt][nt][2]), "+f"(acc[mt][nt][3])
                        : "r"(af[mt][0]), "r"(af[mt][1]), "r"(af[mt][2]), "r"(af[mt][3]),
                          "r"(bf0), "r"(bf1));
                }
            }
        }
        __syncthreads();
    }

    int rel = 2 * rp + wc;
    float qv[16], kv[16];
    #pragma unroll
    for (int nt = 0; nt < 8; nt++) {
        int o0 = nt * 8 + 2 * t;
        qv[2 * nt] = qs[o0]; qv[2 * nt + 1] = qs[o0 + 1];
        kv[2 * nt] = ks[o0]; kv[2 * nt + 1] = ks[o0 + 1];
    }
    __half2* xwh = (__half2*)g_xw;
    #pragma unroll
    for (int mt = 0; mt < 2; mt++) {
        #pragma unroll
        for (int h = 0; h < 2; h++) {
            int row_l = wr * 32 + mt * 16 + g + h * 8;
            int grow = rowBase + row_l;
            bool ok = (grow < M);
            float pq = 0.f, pk = 0.f;
            #pragma unroll
            for (int nt = 0; nt < 8; nt++) {
                float c0 = acc[mt][nt][h * 2 + 0];
                float c1 = acc[mt][nt][h * 2 + 1];
                if (ok) {
                    xwh[((size_t)rel * NN + grow) * 32 + nt * 4 + t] =
                        __floats2half2_rn(c0, c1);
                }
                pq += c0 * qv[2 * nt] + c1 * qv[2 * nt + 1];
                pk += c0 * kv[2 * nt] + c1 * kv[2 * nt + 1];
            }
            pq += __shfl_xor_sync(0xffffffffu, pq, 1);
            pq += __shfl_xor_sync(0xffffffffu, pq, 2);
            pk += __shfl_xor_sync(0xffffffffu, pk, 1);
            pk += __shfl_xor_sync(0xffffffffu, pk, 2);
            if (ok && t == 0) {
                g_sq[rel * NN + grow] = pq;
                g_sk[rel * NN + grow] = pk;
            }
        }
    }
}

// ---------------- segmented softmax-aggregate: one warp per node ----------------
// Fast path gathers uint4 (8 halfs) per lane: 4 edges per warp-round.
// mode 0 additionally accumulates BN statistics (fused k_bnstats).
__global__ void k_agg(const float* __restrict__ b, float* outParam, int mode) {
    __shared__ float ssum[HH], ssq[HH];
    int tid = threadIdx.x;
    if (mode == 0) {
        if (tid < HH) { ssum[tid] = 0.f; ssq[tid] = 0.f; }
        __syncthreads();
    }
    // grid is exactly NN warps (NN*32 threads, divisible by 256)
    int gw = (blockIdx.x * blockDim.x + tid) >> 5;
    int lane = tid & 31;
    int node = gw;
    int beg = g_off[node];
    int cnt = g_cnt[node];

    if (cnt <= 32) {
        int rs_l = 0;
        float a_l = -INFINITY;
        if (lane < cnt) {
            rs_l = g_sorted[beg + lane];
            int r = rs_l / NN;
            float a = g_sq[r * NN + node] + g_sk[rs_l];
            a_l = a > 0.f ? a : 0.2f * a;
        }
        float m = a_l;
        #pragma unroll
        for (int off = 16; off; off >>= 1)
            m = fmaxf(m, __shfl_xor_sync(0xffffffffu, m, off));
        float w_l = (lane < cnt) ? __expf(a_l - m) : 0.f;
        float denom = w_l;
        #pragma unroll
        for (int off = 16; off; off >>= 1)
            denom += __shfl_xor_sync(0xffffffffu, denom, off);

        int grp = lane >> 3, sub = lane & 7;
        float acc8[8] = {0.f, 0.f, 0.f, 0.f, 0.f, 0.f, 0.f, 0.f};
        const uint4* xw4 = (const uint4*)g_xw;
        for (int i = 0; i < cnt; i += 4) {
            int e = i + grp;
            int rs = __shfl_sync(0xffffffffu, rs_l, e & 31);
            float w = __shfl_sync(0xffffffffu, w_l, e & 31);
            if (e < cnt) {
                uint4 v = xw4[(size_t)rs * 8 + sub];
                __half2* hp = (__half2*)&v;
                #pragma unroll
                for (int j = 0; j < 4; j++) {
                    float2 f = __half22float2(hp[j]);
                    acc8[2 * j]     += w * f.x;
                    acc8[2 * j + 1] += w * f.y;
                }
            }
        }
        #pragma unroll
        for (int j = 0; j < 8; j++) {
            acc8[j] += __shfl_xor_sync(0xffffffffu, acc8[j], 8);
            acc8[j] += __shfl_xor_sync(0xffffffffu, acc8[j], 16);
        }
        if (lane < 8) {
            float inv = 1.f / (denom + 1e-16f);
            float4 b0 = ((const float4*)b)[lane * 2];
            float4 b1 = ((const float4*)b)[lane * 2 + 1];
            float o[8];
            o[0] = acc8[0] * inv + b0.x; o[1] = acc8[1] * inv + b0.y;
            o[2] = acc8[2] * inv + b0.z; o[3] = acc8[3] * inv + b0.w;
            o[4] = acc8[4] * inv + b1.x; o[5] = acc8[5] * inv + b1.y;
            o[6] = acc8[6] * inv + b1.z; o[7] = acc8[7] * inv + b1.w;
            if (mode == 1) {
                #pragma unroll
                for (int j = 0; j < 8; j++) o[j] = fmaxf(o[j], 0.f);
                __half2 h0 = __floats2half2_rn(o[0], o[1]);
                __half2 h1 = __floats2half2_rn(o[2], o[3]);
                __half2 h2 = __floats2half2_rn(o[4], o[5]);
                __half2 h3 = __floats2half2_rn(o[6], o[7]);
                uint4 pv = make_uint4(*(uint32_t*)&h0, *(uint32_t*)&h1,
                                      *(uint32_t*)&h2, *(uint32_t*)&h3);
                ((uint4*)g_x1)[(size_t)node * 8 + lane] = pv;
            } else {
                float4 v0 = make_float4(o[0], o[1], o[2], o[3]);
                float4 v1 = make_float4(o[4], o[5], o[6], o[7]);
                ((float4*)outParam)[(size_t)node * 16 + lane * 2]     = v0;
                ((float4*)outParam)[(size_t)node * 16 + lane * 2 + 1] = v1;
                int ch = lane * 8;
                #pragma unroll
                for (int j = 0; j < 8; j++) {
                    atomicAdd(&ssum[ch + j], o[j]);
                    atomicAdd(&ssq[ch + j], o[j] * o[j]);
                }
            }
        }
    } else {
        // general path: per-lane half2 channels
        const __half2* xwh = (const __half2*)g_xw;
        float m = -INFINITY;
        for (int i = lane; i < cnt; i += 32) {
            int rs = g_sorted[beg + i];
            int r = rs / NN;
            float a = g_sq[r * NN + node] + g_sk[rs];
            a = a > 0.f ? a : 0.2f * a;
            m = fmaxf(m, a);
        }
        #pragma unroll
        for (int off = 16; off; off >>= 1)
            m = fmaxf(m, __shfl_xor_sync(0xffffffffu, m, off));
        float2 acc = make_float2(0.f, 0.f);
        float denom = 0.f;
        for (int i = 0; i < cnt; i++) {
            int rs = g_sorted[beg + i];
            int r = rs / NN;
            float a = g_sq[r * NN + node] + g_sk[rs];
            a = a > 0.f ? a : 0.2f * a;
            float w = __expf(a - m);
            denom += w;
            float2 v = __half22float2(xwh[(size_t)rs * 32 + lane]);
            acc.x += w * v.x;
            acc.y += w * v.y;
        }
        float inv = 1.f / (denom + 1e-16f);
        float2 bb = ((const float2*)b)[lane];
        float ox = acc.x * inv + bb.x;
        float oy = acc.y * inv + bb.y;
        if (mode == 1) {
            ox = fmaxf(ox, 0.f); oy = fmaxf(oy, 0.f);
            ((__half2*)g_x1)[(size_t)node * 32 + lane] = __floats2half2_rn(ox, oy);
        } else {
            ((float2*)outParam)[(size_t)node * 32 + lane] = make_float2(ox, oy);
            atomicAdd(&ssum[2 * lane], ox);
            atomicAdd(&ssq[2 * lane], ox * ox);
            atomicAdd(&ssum[2 * lane + 1], oy);
            atomicAdd(&ssq[2 * lane + 1], oy * oy);
        }
    }

    if (mode == 0) {
        __syncthreads();
        if (tid < HH) {
            atomicAdd(&g_bnsum[tid], ssum[tid]);
            atomicAdd(&g_bnsqs[tid], ssq[tid]);
        }
    }
}

// ---------------- batchnorm ----------------
__global__ void k_bnfinal(const float* __restrict__ gamma, const float* __restrict__ beta) {
    int h = threadIdx.x;
    if (h < HH) {
        float mean = g_bnsum[h] * (1.f / NN);
        float var  = g_bnsqs[h] * (1.f / NN) - mean * mean;
        float sc = gamma[h] * rsqrtf(var + 1e-5f);
        g_bnscale[h] = sc;
        g_bnshift[h] = beta[h] - mean * sc;
    }
}

__global__ void k_bnapply(float* __restrict__ out) {
    int t = blockIdx.x * blockDim.x + threadIdx.x;
    if (t >= NN * 16) return;
    int h4 = t & 15;
    float4 v  = ((float4*)out)[t];
    float4 sc = ((const float4*)g_bnscale)[h4];
    float4 sh = ((const float4*)g_bnshift)[h4];
    v.x = v.x * sc.x + sh.x; v.x = v.x > 0.f ? v.x : 0.01f * v.x;
    v.y = v.y * sc.y + sh.y; v.y = v.y > 0.f ? v.y : 0.01f * v.y;
    v.z = v.z * sc.z + sh.z; v.z = v.z > 0.f ? v.z : 0.01f * v.z;
    v.w = v.w * sc.w + sh.w; v.w = v.w > 0.f ? v.w : 0.01f * v.w;
    ((float4*)out)[t] = v;
}

// ---------------- launch ----------------
extern "C" void kernel_launch(void* const* d_in, const int* in_sizes, int n_in,
                              void* d_out, int out_size) {
    const float* x     = (const float*)d_in[0];
    const int*   ei    = (const int*)d_in[1];
    const int*   et    = (const int*)d_in[2];
    const float* W1    = (const float*)d_in[3];
    const float* q1    = (const float*)d_in[4];
    const float* k1    = (const float*)d_in[5];
    const float* b1    = (const float*)d_in[6];
    const float* W2    = (const float*)d_in[7];
    const float* q2    = (const float*)d_in[8];
    const float* k2    = (const float*)d_in[9];
    const float* b2    = (const float*)d_in[10];
    const float* gamma = (const float*)d_in[11];
    const float* beta  = (const float*)d_in[12];
    float* out = (float*)d_out;

    const int TPB = 256;
    dim3 gemmGrid(4, (NN + 127) / 128);

    k_prep<<<(NN * 32 + TPB - 1) / TPB, TPB>>>(x, W1, W2);         // 0
    k_decode<<<(EE + TPB - 1) / TPB, TPB>>>(ei, et);               // 1
    k_scan1<<<NBLK, SCAN_B>>>();                                   // 2
    k_gemm<<<gemmGrid, TPB>>>(NN, GG, 0, q1, k1);                  // 3 <- profiled
    k_scan2<<<1, 256>>>();                                         // 4
    k_scan3<<<(NN + TPB - 1) / TPB, TPB>>>();                      // 5
    k_scatter<<<(EE + TPB - 1) / TPB, TPB>>>();                    // 6
    k_agg<<<NN * 32 / TPB, TPB>>>(b1, nullptr, 1);                 // 7

    // ---- layer 2 ----
    k_gemm<<<gemmGrid, TPB>>>(NN, HH, 1, q2, k2);                  // 8
    k_agg<<<NN * 32 / TPB, TPB>>>(b2, out, 0);                     // 9

    // ---- batchnorm + leaky ----
    k_bnfinal<<<1, HH>>>(gamma, beta);                             // 10
    k_bnapply<<<(NN * 16 + TPB - 1) / TPB, TPB>>>(out);            // 11
}

// round 17
// speedup vs baseline: 1.1157x; 1.0509x over previous
#include <cuda_runtime.h>
#include <cuda_fp16.h>
#include <math.h>
#include <stdint.h>

#define NN 100000
#define EE 1600000
#define RR 8
#define GG 128
#define HH 64
#define CC 512   // RR*HH
#define SCAN_B 512
#define NBLK ((NN + SCAN_B - 1) / SCAN_B)   // 196

// ---------------- scratch ----------------
__device__ __half g_xw[(size_t)RR * NN * HH];  // [r][n][h] fp16
__device__ __half g_xa[(size_t)NN * GG];       // fp16 input features
__device__ __half g_WT[GG * CC];               // layer1 W: [r*64+o][k]
__device__ __half g_WT2[HH * CC];              // layer2 W: [r*64+o][k]
__device__ float g_sq[RR * NN];
__device__ float g_sk[RR * NN];
__device__ int   g_rs[EE];
__device__ int   g_dstl[EE];
__device__ int   g_rank[EE];
__device__ int   g_sorted[EE];
__device__ int   g_cnt[NN];
__device__ int   g_off[NN];
__device__ int   g_scan[NN];
__device__ int   g_bsum[256];
__device__ int   g_bpre[256];
__device__ __half g_x1[NN * HH];               // fp16 layer-1 output
__device__ float g_bnsum[HH];
__device__ float g_bnsqs[HH];

// ---------------- fused prep: cvtA + wt1 + wt2 + zeroing ----------------
__global__ void k_prep(const float* __restrict__ x,
                       const float* __restrict__ W1,
                       const float* __restrict__ W2) {
    int i = blockIdx.x * blockDim.x + threadIdx.x;
    if (i < NN * (GG / 4)) {
        float4 v = ((const float4*)x)[i];
        __half2 h0 = __floats2half2_rn(v.x, v.y);
        __half2 h1 = __floats2half2_rn(v.z, v.w);
        ((uint2*)g_xa)[i] = make_uint2(*(uint32_t*)&h0, *(uint32_t*)&h1);
    }
    if (i < GG * CC) {
        int c = i / GG, k = i % GG;
        int r = c >> 6, o = c & 63;
        g_WT[i] = __float2half_rn(W1[((size_t)r * GG + k) * HH + o]);
    }
    if (i < HH * CC) {
        int c = i / HH, k = i % HH;
        int r = c >> 6, o = c & 63;
        g_WT2[i] = __float2half_rn(W2[((size_t)r * HH + k) * HH + o]);
    }
    if (i < NN) g_cnt[i] = 0;
    if (i < HH) { g_bnsum[i] = 0.f; g_bnsqs[i] = 0.f; }
}

// ---------------- sort-by-dst pipeline ----------------
__global__ void k_decode(const int* __restrict__ ei, const int* __restrict__ et) {
    int e = blockIdx.x * blockDim.x + threadIdx.x;
    if (e >= EE) return;
    int s = min(max(ei[e], 0), NN - 1);
    int d = min(max(ei[EE + e], 0), NN - 1);
    int r = min(max(et[e], 0), RR - 1);
    g_rs[e]   = r * NN + s;
    g_dstl[e] = d;
    g_rank[e] = atomicAdd(&g_cnt[d], 1);
}

__global__ void k_scan1() {
    __shared__ int s[SCAN_B];
    int tid = threadIdx.x;
    int i = blockIdx.x * SCAN_B + tid;
    int v = (i < NN) ? g_cnt[i] : 0;
    s[tid] = v;
    __syncthreads();
    for (int d = 1; d < SCAN_B; d <<= 1) {
        int t = (tid >= d) ? s[tid - d] : 0;
        __syncthreads();
        s[tid] += t;
        __syncthreads();
    }
    if (i < NN) g_scan[i] = s[tid];
    if (tid == SCAN_B - 1) g_bsum[blockIdx.x] = s[tid];
}

__global__ void k_scan2() {
    __shared__ int s[256];
    int tid = threadIdx.x;
    int v = (tid < NBLK) ? g_bsum[tid] : 0;
    s[tid] = v;
    __syncthreads();
    for (int d = 1; d < 256; d <<= 1) {
        int t = (tid >= d) ? s[tid - d] : 0;
        __syncthreads();
        s[tid] += t;
        __syncthreads();
    }
    if (tid < NBLK) g_bpre[tid] = s[tid] - v;
}

__global__ void k_scan3() {
    int i = blockIdx.x * blockDim.x + threadIdx.x;
    if (i >= NN) return;
    g_off[i] = g_scan[i] - g_cnt[i] + g_bpre[i >> 9];
}

__global__ void k_scatter() {
    int e = blockIdx.x * blockDim.x + threadIdx.x;
    if (e >= EE) return;
    g_sorted[g_off[g_dstl[e]] + g_rank[e]] = g_rs[e];
}

// ---------------- fp16 tensor-core GEMM + fused scores ----------------
#define PADH 40

__device__ __forceinline__ void cpa16(uint32_t smem_addr, const void* gptr, int sz) {
    asm volatile("cp.async.ca.shared.global [%0], [%1], 16, %2;\n"
                 :: "r"(smem_addr), "l"(gptr), "r"(sz));
}

__global__ void __launch_bounds__(256)
k_gemm(int M, int K, int useX1,
       const float* __restrict__ qv_g, const float* __restrict__ kv_g) {
    const __half* __restrict__ A = useX1 ? g_x1 : g_xa;
    const __half* __restrict__ WT = useX1 ? g_WT2 : g_WT;
    __shared__ __half Ah[2][128 * PADH];
    __shared__ __half Bh[2][128 * PADH];
    __shared__ float qs[64], ks[64];

    int rp = blockIdx.x;
    int rowBase = blockIdx.y * 128;
    int tid = threadIdx.x;
    int warp = tid >> 5, lane = tid & 31;
    int wr = warp >> 1, wc = warp & 1;
    int g = lane >> 2, t = lane & 3;

    uint32_t AhS0 = (uint32_t)__cvta_generic_to_shared(Ah[0]);
    uint32_t AhS1 = (uint32_t)__cvta_generic_to_shared(Ah[1]);
    uint32_t BhS0 = (uint32_t)__cvta_generic_to_shared(Bh[0]);
    uint32_t BhS1 = (uint32_t)__cvta_generic_to_shared(Bh[1]);

    if (tid < 64)        qs[tid] = qv_g[tid];
    else if (tid < 128)  ks[tid - 64] = kv_g[tid - 64];

    float acc[2][8][4];
    #pragma unroll
    for (int i = 0; i < 2; i++)
        #pragma unroll
        for (int j = 0; j < 8; j++)
            #pragma unroll
            for (int l = 0; l < 4; l++) acc[i][j][l] = 0.f;

    int nChunks = K >> 5;
    int lrow = tid >> 1;
    int lc8  = (tid & 1) * 8;
    int lm_row = (lane & 7) + ((lane >> 3) & 1) * 8;
    int lm_c8  = (lane >> 4) * 8;
    int bl_row = lane & 7;
    int bl_k8  = ((lane >> 3) & 1) * 8;
    int grow_l = rowBase + lrow;
    bool okA = (grow_l < M);
    const __half* aSrc = A + (size_t)grow_l * K;
    const __half* bSrc = WT + (size_t)(rp * 128 + lrow) * K;

    #pragma unroll
    for (int p = 0; p < 2; p++) {
        int c8 = lc8 + p * 16;
        cpa16(AhS0 + (lrow * PADH + c8) * 2, aSrc + c8, okA ? 16 : 0);
        cpa16(BhS0 + (lrow * PADH + c8) * 2, bSrc + c8, 16);
    }
    asm volatile("cp.async.commit_group;\n");

    for (int c = 0; c < nChunks; c++) {
        int cur = c & 1;
        if (c + 1 < nChunks) {
            int kb = (c + 1) << 5;
            uint32_t AhN = cur ? AhS0 : AhS1;
            uint32_t BhN = cur ? BhS0 : BhS1;
            #pragma unroll
            for (int p = 0; p < 2; p++) {
                int c8 = lc8 + p * 16;
                cpa16(AhN + (lrow * PADH + c8) * 2, aSrc + kb + c8, okA ? 16 : 0);
                cpa16(BhN + (lrow * PADH + c8) * 2, bSrc + kb + c8, 16);
            }
            asm volatile("cp.async.commit_group;\n");
            asm volatile("cp.async.wait_group 1;\n");
        } else {
            asm volatile("cp.async.wait_group 0;\n");
        }
        __syncthreads();

        uint32_t AhC = cur ? AhS1 : AhS0;
        uint32_t BhC = cur ? BhS1 : BhS0;

        #pragma unroll
        for (int ks16 = 0; ks16 < 2; ks16++) {
            uint32_t af[2][4];
            #pragma unroll
            for (int mt = 0; mt < 2; mt++) {
                int row = wr * 32 + mt * 16 + lm_row;
                uint32_t addr = AhC + (row * PADH + ks16 * 16 + lm_c8) * 2;
                asm volatile(
                    "ldmatrix.sync.aligned.m8n8.x4.shared.b16 {%0,%1,%2,%3}, [%4];\n"
                    : "=r"(af[mt][0]), "=r"(af[mt][1]), "=r"(af[mt][2]), "=r"(af[mt][3])
                    : "r"(addr));
            }
            #pragma unroll
            for (int nt = 0; nt < 8; nt++) {
                int nbase = wc * 64 + nt * 8;
                uint32_t bf0, bf1;
                uint32_t baddr = BhC +
                    ((nbase + bl_row) * PADH + ks16 * 16 + bl_k8) * 2;
                asm volatile(
                    "ldmatrix.sync.aligned.m8n8.x2.shared.b16 {%0,%1}, [%2];\n"
                    : "=r"(bf0), "=r"(bf1) : "r"(baddr));
                #pragma unroll
                for (int mt = 0; mt < 2; mt++) {
                    asm volatile(
                        "mma.sync.aligned.m16n8k16.row.col.f32.f16.f16.f32 "
                        "{%0,%1,%2,%3}, {%4,%5,%6,%7}, {%8,%9}, {%0,%1,%2,%3};\n"
                        : "+f"(acc[mt][nt][0]), "+f"(acc[mt][nt][1]),
                          "+f"(acc[mt][nt][2]), "+f"(acc[mt][nt][3])
                        : "r"(af[mt][0]), "r"(af[mt][1]), "r"(af[mt][2]), "r"(af[mt][3]),
                          "r"(bf0), "r"(bf1));
                }
            }
        }
        __syncthreads();
    }

    int rel = 2 * rp + wc;
    float qv[16], kv[16];
    #pragma unroll
    for (int nt = 0; nt < 8; nt++) {
        int o0 = nt * 8 + 2 * t;
        qv[2 * nt] = qs[o0]; qv[2 * nt + 1] = qs[o0 + 1];
        kv[2 * nt] = ks[o0]; kv[2 * nt + 1] = ks[o0 + 1];
    }
    __half2* xwh = (__half2*)g_xw;
    #pragma unroll
    for (int mt = 0; mt < 2; mt++) {
        #pragma unroll
        for (int h = 0; h < 2; h++) {
            int row_l = wr * 32 + mt * 16 + g + h * 8;
            int grow = rowBase + row_l;
            bool ok = (grow < M);
            float pq = 0.f, pk = 0.f;
            #pragma unroll
            for (int nt = 0; nt < 8; nt++) {
                float c0 = acc[mt][nt][h * 2 + 0];
                float c1 = acc[mt][nt][h * 2 + 1];
                if (ok) {
                    xwh[((size_t)rel * NN + grow) * 32 + nt * 4 + t] =
                        __floats2half2_rn(c0, c1);
                }
                pq += c0 * qv[2 * nt] + c1 * qv[2 * nt + 1];
                pk += c0 * kv[2 * nt] + c1 * kv[2 * nt + 1];
            }
            pq += __shfl_xor_sync(0xffffffffu, pq, 1);
            pq += __shfl_xor_sync(0xffffffffu, pq, 2);
            pk += __shfl_xor_sync(0xffffffffu, pk, 1);
            pk += __shfl_xor_sync(0xffffffffu, pk, 2);
            if (ok && t == 0) {
                g_sq[rel * NN + grow] = pq;
                g_sk[rel * NN + grow] = pk;
            }
        }
    }
}

// ---------------- segmented softmax-aggregate: one warp per node ----------------
// Fast path: 4 edges/round (8 lanes x uint4 per edge) with one-round prefetch
// to double memory-level parallelism. mode 0 also accumulates BN statistics.
__global__ void k_agg(const float* __restrict__ b, float* outParam, int mode) {
    __shared__ float ssum[HH], ssq[HH];
    int tid = threadIdx.x;
    if (mode == 0) {
        if (tid < HH) { ssum[tid] = 0.f; ssq[tid] = 0.f; }
        __syncthreads();
    }
    int gw = (blockIdx.x * blockDim.x + tid) >> 5;
    int lane = tid & 31;
    int node = gw;
    int beg = g_off[node];
    int cnt = g_cnt[node];

    if (cnt <= 32) {
        int rs_l = 0;
        float a_l = -INFINITY;
        if (lane < cnt) {
            rs_l = g_sorted[beg + lane];
            int r = rs_l / NN;
            float a = g_sq[r * NN + node] + g_sk[rs_l];
            a_l = a > 0.f ? a : 0.2f * a;
        }
        float m = a_l;
        #pragma unroll
        for (int off = 16; off; off >>= 1)
            m = fmaxf(m, __shfl_xor_sync(0xffffffffu, m, off));
        float w_l = (lane < cnt) ? __expf(a_l - m) : 0.f;
        float denom = w_l;
        #pragma unroll
        for (int off = 16; off; off >>= 1)
            denom += __shfl_xor_sync(0xffffffffu, denom, off);

        int grp = lane >> 3, sub = lane & 7;
        float acc8[8] = {0.f, 0.f, 0.f, 0.f, 0.f, 0.f, 0.f, 0.f};
        const uint4* xw4 = (const uint4*)g_xw;

        // prefetch round 0
        uint4 v0 = make_uint4(0, 0, 0, 0);
        float w0;
        {
            int e0 = grp;
            int e0c = (e0 < cnt) ? e0 : 0;
            int rs0 = __shfl_sync(0xffffffffu, rs_l, e0c);
            w0 = __shfl_sync(0xffffffffu, w_l, e0c);
            if (e0 < cnt) v0 = xw4[(size_t)rs0 * 8 + sub];
        }
        for (int i = 0; i < cnt; i += 4) {
            // prefetch round i+4 while accumulating round i
            int e1 = i + 4 + grp;
            int e1c = (e1 < cnt) ? e1 : 0;
            int rs1 = __shfl_sync(0xffffffffu, rs_l, e1c);
            float w1 = __shfl_sync(0xffffffffu, w_l, e1c);
            uint4 v1 = make_uint4(0, 0, 0, 0);
            if (e1 < cnt) v1 = xw4[(size_t)rs1 * 8 + sub];

            __half2* hp = (__half2*)&v0;   // v0 is zero when this group's edge is OOB
            #pragma unroll
            for (int j = 0; j < 4; j++) {
                float2 f = __half22float2(hp[j]);
                acc8[2 * j]     += w0 * f.x;
                acc8[2 * j + 1] += w0 * f.y;
            }
            v0 = v1; w0 = w1;
        }
        #pragma unroll
        for (int j = 0; j < 8; j++) {
            acc8[j] += __shfl_xor_sync(0xffffffffu, acc8[j], 8);
            acc8[j] += __shfl_xor_sync(0xffffffffu, acc8[j], 16);
        }
        if (lane < 8) {
            float inv = 1.f / (denom + 1e-16f);
            float4 b0 = ((const float4*)b)[lane * 2];
            float4 b1 = ((const float4*)b)[lane * 2 + 1];
            float o[8];
            o[0] = acc8[0] * inv + b0.x; o[1] = acc8[1] * inv + b0.y;
            o[2] = acc8[2] * inv + b0.z; o[3] = acc8[3] * inv + b0.w;
            o[4] = acc8[4] * inv + b1.x; o[5] = acc8[5] * inv + b1.y;
            o[6] = acc8[6] * inv + b1.z; o[7] = acc8[7] * inv + b1.w;
            if (mode == 1) {
                #pragma unroll
                for (int j = 0; j < 8; j++) o[j] = fmaxf(o[j], 0.f);
                __half2 h0 = __floats2half2_rn(o[0], o[1]);
                __half2 h1 = __floats2half2_rn(o[2], o[3]);
                __half2 h2 = __floats2half2_rn(o[4], o[5]);
                __half2 h3 = __floats2half2_rn(o[6], o[7]);
                uint4 pv = make_uint4(*(uint32_t*)&h0, *(uint32_t*)&h1,
                                      *(uint32_t*)&h2, *(uint32_t*)&h3);
                ((uint4*)g_x1)[(size_t)node * 8 + lane] = pv;
            } else {
                float4 v0o = make_float4(o[0], o[1], o[2], o[3]);
                float4 v1o = make_float4(o[4], o[5], o[6], o[7]);
                ((float4*)outParam)[(size_t)node * 16 + lane * 2]     = v0o;
                ((float4*)outParam)[(size_t)node * 16 + lane * 2 + 1] = v1o;
                int ch = lane * 8;
                #pragma unroll
                for (int j = 0; j < 8; j++) {
                    atomicAdd(&ssum[ch + j], o[j]);
                    atomicAdd(&ssq[ch + j], o[j] * o[j]);
                }
            }
        }
    } else {
        const __half2* xwh = (const __half2*)g_xw;
        float m = -INFINITY;
        for (int i = lane; i < cnt; i += 32) {
            int rs = g_sorted[beg + i];
            int r = rs / NN;
            float a = g_sq[r * NN + node] + g_sk[rs];
            a = a > 0.f ? a : 0.2f * a;
            m = fmaxf(m, a);
        }
        #pragma unroll
        for (int off = 16; off; off >>= 1)
            m = fmaxf(m, __shfl_xor_sync(0xffffffffu, m, off));
        float2 acc = make_float2(0.f, 0.f);
        float denom = 0.f;
        for (int i = 0; i < cnt; i++) {
            int rs = g_sorted[beg + i];
            int r = rs / NN;
            float a = g_sq[r * NN + node] + g_sk[rs];
            a = a > 0.f ? a : 0.2f * a;
            float w = __expf(a - m);
            denom += w;
            float2 v = __half22float2(xwh[(size_t)rs * 32 + lane]);
            acc.x += w * v.x;
            acc.y += w * v.y;
        }
        float inv = 1.f / (denom + 1e-16f);
        float2 bb = ((const float2*)b)[lane];
        float ox = acc.x * inv + bb.x;
        float oy = acc.y * inv + bb.y;
        if (mode == 1) {
            ox = fmaxf(ox, 0.f); oy = fmaxf(oy, 0.f);
            ((__half2*)g_x1)[(size_t)node * 32 + lane] = __floats2half2_rn(ox, oy);
        } else {
            ((float2*)outParam)[(size_t)node * 32 + lane] = make_float2(ox, oy);
            atomicAdd(&ssum[2 * lane], ox);
            atomicAdd(&ssq[2 * lane], ox * ox);
            atomicAdd(&ssum[2 * lane + 1], oy);
            atomicAdd(&ssq[2 * lane + 1], oy * oy);
        }
    }

    if (mode == 0) {
        __syncthreads();
        if (tid < HH) {
            atomicAdd(&g_bnsum[tid], ssum[tid]);
            atomicAdd(&g_bnsqs[tid], ssq[tid]);
        }
    }
}

// ---------------- batchnorm finalize + apply (fused) ----------------
__global__ void k_bnapply(const float* __restrict__ gamma,
                          const float* __restrict__ beta,
                          float* __restrict__ out) {
    __shared__ float sc[HH], sh[HH];
    int tid = threadIdx.x;
    if (tid < HH) {
        float mean = g_bnsum[tid] * (1.f / NN);
        float var  = g_bnsqs[tid] * (1.f / NN) - mean * mean;
        float s = gamma[tid] * rsqrtf(var + 1e-5f);
        sc[tid] = s;
        sh[tid] = beta[tid] - mean * s;
    }
    __syncthreads();
    int t = blockIdx.x * blockDim.x + tid;
    if (t >= NN * 16) return;
    int h4 = t & 15;
    float4 v   = ((float4*)out)[t];
    float4 scv = ((const float4*)sc)[h4];
    float4 shv = ((const float4*)sh)[h4];
    v.x = v.x * scv.x + shv.x; v.x = v.x > 0.f ? v.x : 0.01f * v.x;
    v.y = v.y * scv.y + shv.y; v.y = v.y > 0.f ? v.y : 0.01f * v.y;
    v.z = v.z * scv.z + shv.z; v.z = v.z > 0.f ? v.z : 0.01f * v.z;
    v.w = v.w * scv.w + shv.w; v.w = v.w > 0.f ? v.w : 0.01f * v.w;
    ((float4*)out)[t] = v;
}

// ---------------- launch ----------------
extern "C" void kernel_launch(void* const* d_in, const int* in_sizes, int n_in,
                              void* d_out, int out_size) {
    const float* x     = (const float*)d_in[0];
    const int*   ei    = (const int*)d_in[1];
    const int*   et    = (const int*)d_in[2];
    const float* W1    = (const float*)d_in[3];
    const float* q1    = (const float*)d_in[4];
    const float* k1    = (const float*)d_in[5];
    const float* b1    = (const float*)d_in[6];
    const float* W2    = (const float*)d_in[7];
    const float* q2    = (const float*)d_in[8];
    const float* k2    = (const float*)d_in[9];
    const float* b2    = (const float*)d_in[10];
    const float* gamma = (const float*)d_in[11];
    const float* beta  = (const float*)d_in[12];
    float* out = (float*)d_out;

    const int TPB = 256;
    dim3 gemmGrid(4, (NN + 127) / 128);

    k_prep<<<(NN * 32 + TPB - 1) / TPB, TPB>>>(x, W1, W2);         // 0
    k_decode<<<(EE + TPB - 1) / TPB, TPB>>>(ei, et);               // 1
    k_scan1<<<NBLK, SCAN_B>>>();                                   // 2
    k_gemm<<<gemmGrid, TPB>>>(NN, GG, 0, q1, k1);                  // 3 <- profiled
    k_scan2<<<1, 256>>>();                                         // 4
    k_scan3<<<(NN + TPB - 1) / TPB, TPB>>>();                      // 5
    k_scatter<<<(EE + TPB - 1) / TPB, TPB>>>();                    // 6
    k_agg<<<NN * 32 / TPB, TPB>>>(b1, nullptr, 1);                 // 7

    // ---- layer 2 ----
    k_gemm<<<gemmGrid, TPB>>>(NN, HH, 1, q2, k2);                  // 8
    k_agg<<<NN * 32 / TPB, TPB>>>(b2, out, 0);                     // 9

    // ---- batchnorm + leaky (fused finalize+apply) ----
    k_bnapply<<<(NN * 16 + TPB - 1) / TPB, TPB>>>(gamma, beta, out); // 10
}